// round 16
// baseline (speedup 1.0000x reference)
#include <cuda_runtime.h>
#include <cuda_bf16.h>
#include <cstdint>

// Problem constants
#define BB 64
#define KK 64
#define DD 128
#define HH 128
#define TT 4
#define ROWS (BB*KK)        // 4096
#define EPSLN 1e-5f

// ---------------- scratch (no allocations allowed) ----------------
__device__ __align__(16) float g_HDS[ROWS*DD];
__device__ __align__(16) float g_H  [ROWS*DD];
__device__ __align__(16) float g_W  [ROWS*TT];          // [row][tau]
__device__ __align__(16) float g_Wm [TT*BB*64*64];      // [tau][b][i][j] = ep*et
__device__ __align__(16) __nv_bfloat16 g_Ab [TT*ROWS*HH];
__device__ __align__(16) __nv_bfloat16 g_Bb [TT*ROWS*HH];
__device__ __align__(16) __nv_bfloat16 g_Sb [ROWS*TT*HH];   // [row][tau*128+n]

// prepped weights: bf16, [n][k-pair] chunked (4096 words per 64-k chunk)
#define W_WS1   0
#define W_WS2   8192
#define W_WU2   16384
#define W_WI3   24576
#define W_WU1   57344
#define W_WI1   73728
#define W_WI2F  139264
#define W_TOTAL 172032
#define PREP_TOTAL (W_TOTAL + TT*BB*64*64)
__device__ __align__(16) uint32_t g_Wp[W_TOTAL];

// ---------------- helpers ----------------
__device__ __forceinline__ uint32_t pk2(float lo, float hi){
    __nv_bfloat162 v = __floats2bfloat162_rn(lo, hi);
    return *(uint32_t*)&v;
}
__device__ __forceinline__ uint32_t addrelu2(uint32_t a, uint32_t b){
    __nv_bfloat162 av = *(__nv_bfloat162*)&a;
    __nv_bfloat162 bv = *(__nv_bfloat162*)&b;
    __nv_bfloat162 z  = __float2bfloat162_rn(0.f);
    __nv_bfloat162 r  = __hmax2(__hadd2(av, bv), z);
    return *(uint32_t*)&r;
}
__device__ __forceinline__ void mma16816(float c[4], const uint32_t a[4],
                                         uint32_t b0, uint32_t b1){
    asm volatile(
        "mma.sync.aligned.m16n8k16.row.col.f32.bf16.bf16.f32 "
        "{%0,%1,%2,%3}, {%4,%5,%6,%7}, {%8,%9}, {%0,%1,%2,%3};\n"
        : "+f"(c[0]), "+f"(c[1]), "+f"(c[2]), "+f"(c[3])
        : "r"(a[0]), "r"(a[1]), "r"(a[2]), "r"(a[3]), "r"(b0), "r"(b1));
}
__device__ __forceinline__ void ldmx4(uint32_t r[4], uint32_t a){
    asm volatile("ldmatrix.sync.aligned.m8n8.x4.shared.b16 {%0,%1,%2,%3}, [%4];"
        : "=r"(r[0]), "=r"(r[1]), "=r"(r[2]), "=r"(r[3]) : "r"(a));
}
__device__ __forceinline__ uint32_t s2u(const void* p){
    return (uint32_t)__cvta_generic_to_shared((void*)p);
}
__device__ __forceinline__ void cpa16(uint32_t dst, const void* src){
    asm volatile("cp.async.cg.shared.global [%0], [%1], 16;"
                 :: "r"(dst), "l"(src) : "memory");
}
#define CPA_COMMIT() asm volatile("cp.async.commit_group;" ::: "memory")
#define CPA_WAIT1()  asm volatile("cp.async.wait_group 1;" ::: "memory")

// ---------------- weight prep + pair-weight precompute ----------------
__global__ void __launch_bounds__(256) prep_weights(
    const float* __restrict__ ws1, const float* __restrict__ ws2,
    const float* __restrict__ wu2, const float* __restrict__ wi3,
    const float* __restrict__ wu1, const float* __restrict__ wi1,
    const float* __restrict__ wi2,
    const float* __restrict__ ep,  const float* __restrict__ et)
{
    int idx = blockIdx.x*256 + threadIdx.x;
    if (idx >= PREP_TOTAL) return;
    if (idx >= W_TOTAL) {
        int m = idx - W_TOTAL;          // [tau][b][i][j]
        int j = m & 63, i = (m >> 6) & 63, b = (m >> 12) & 63, tau = m >> 18;
        size_t pid = ((size_t)b*64 + i)*64 + j;
        g_Wm[m] = ep[pid] * et[pid*4 + tau];
        return;
    }
    const float* src;
    int local;
    if (idx < W_WS2)       { src = ws1; local = idx - W_WS1; }
    else if (idx < W_WU2)  { src = ws2; local = idx - W_WS2; }
    else if (idx < W_WI3)  { src = wu2; local = idx - W_WU2; }
    else if (idx < W_WU1)  { src = wi3; local = idx - W_WI3; }
    else if (idx < W_WI1)  { src = wu1; local = idx - W_WU1; }
    else if (idx < W_WI2F) {
        int l = idx - W_WI1;
        int tau = l >> 14;
        src = wi1 + (size_t)tau*256*128;
        local = l & 16383;
    } else {
        int l = idx - W_WI2F;
        int tau = l >> 13;
        int r = l & 8191;
        int n = r >> 6, w = r & 63;
        const float* s = wi2 + (size_t)tau*16384;
        g_Wp[idx] = pk2(s[(size_t)(2*w)*128 + n], s[(size_t)(2*w+1)*128 + n]);
        return;
    }
    int c = local >> 12;
    int r = local & 4095;
    int n = r >> 5, w = r & 31;
    int k = c*64 + 2*w;
    g_Wp[idx] = pk2(src[(size_t)k*128 + n], src[(size_t)(k+1)*128 + n]);
}

// ---------------- pipelined GEMM primitives (512-thread glue) ---------------
// 32 rows x 128 n x 64 k per chunk; 16 warps: warp_m = wid>>3, warp_n8 = wid&7
// (16 cols each). Per-warp tile 16x16.
#define GSTR 36
#define WBUF_BYTES 18432
#define UNIT_BYTES (2*WBUF_BYTES)

__device__ __forceinline__ void prefW5(uint32_t dstBase,
                                       const uint32_t* __restrict__ Wg, int tid){
    #pragma unroll
    for (int l = 0; l < 2; l++) {
        int u = tid + l*512;
        int n = u >> 3, w0 = (u & 7)*4;
        cpa16(dstBase + (uint32_t)(n*GSTR + w0)*4, Wg + u*4);
    }
}
__device__ __forceinline__ void prefS5(uint32_t dstBase,
                                       const __nv_bfloat16* __restrict__ Sb,
                                       int rowBase, int c8, int tid){
    if (tid < 256) {
        int lr = tid >> 3, uu = tid & 7;
        cpa16(dstBase + (uint32_t)(lr*36 + uu*4)*4,
              (const uint4*)Sb + (size_t)(rowBase+lr)*64 + c8*8 + uu);
    }
}
__device__ __forceinline__ void cmpW5(
    float (&c)[2][4], uint32_t smB, int wtOff,
    int aOff, int astr, int aChunkOff, int tid)
{
    int lane = tid & 31, wid = tid >> 5;
    int warp_m = wid >> 3, warp_n8 = wid & 7;
    int lA_row = lane & 15, lA_kw = (lane >> 4) << 2;
    int lB_row = (lane & 7) + ((lane >> 4) << 3);
    int lB_kw  = ((lane >> 3) & 1) << 2;
    uint32_t AsB = smB + aOff, WtB = smB + (uint32_t)wtOff;
    #pragma unroll
    for (int kk = 0; kk < 4; kk++) {
        uint32_t wf[4], a[4];
        ldmx4(wf, WtB + ((warp_n8*16 + lB_row)*GSTR + kk*8 + lB_kw)*4);
        ldmx4(a, AsB + ((warp_m*16 + lA_row)*astr + aChunkOff + kk*8 + lA_kw)*4);
        mma16816(c[0], a, wf[0], wf[1]);
        mma16816(c[1], a, wf[2], wf[3]);
    }
}

// ---------------- megaA: LN128 + self-MLP + wi1 (512 thr, unit-batched) -----
#define MA_HS   0
#define MA_XN   16384
#define MA_HB   25088
#define MA_T1   33792
#define MA_W0   42496
#define MA_TOT  116224

__device__ __forceinline__ const uint32_t* ma_unit(int u){
    if (u == 0) return g_Wp + W_WS1;
    if (u == 1) return g_Wp + W_WS2;
    return g_Wp + W_WI1 + (u-2)*8192;
}

__global__ void __launch_bounds__(512) megaA_kernel(
    const float* __restrict__ h,
    const float* __restrict__ ls_g, const float* __restrict__ ls_b,
    const float* __restrict__ bs1, const float* __restrict__ bs2,
    const float* __restrict__ bi1,
    float* __restrict__ HDS, __nv_bfloat16* __restrict__ Ab,
    __nv_bfloat16* __restrict__ Bb)
{
    extern __shared__ char sm[];
    float* Hs = (float*)(sm + MA_HS);
    uint32_t* XN = (uint32_t*)(sm + MA_XN);
    uint32_t* HB = (uint32_t*)(sm + MA_HB);
    uint32_t* T1 = (uint32_t*)(sm + MA_T1);
    uint32_t smB = s2u(sm);
    int tid = threadIdx.x, lane = tid & 31, wid = tid >> 5;
    int rowBase = blockIdx.x * 32;
    int g = lane >> 2, q4 = lane & 3;
    int warp_m = wid >> 3, warp_n8 = wid & 7;
    int row0 = warp_m*16 + g, row1 = row0 + 8;

    prefW5(smB + MA_W0,              ma_unit(0),        tid);
    prefW5(smB + MA_W0 + WBUF_BYTES, ma_unit(0) + 4096, tid);
    CPA_COMMIT();
    prefW5(smB + MA_W0 + UNIT_BYTES,              ma_unit(1),        tid);
    prefW5(smB + MA_W0 + UNIT_BYTES + WBUF_BYTES, ma_unit(1) + 4096, tid);
    CPA_COMMIT();

    #pragma unroll
    for (int l = 0; l < 2; l++) {
        int u = tid + l*512;
        int r = u >> 5, q = u & 31;
        *(float4*)&Hs[r*128 + q*4] =
            *(const float4*)&h[(size_t)(rowBase+r)*128 + q*4];
    }
    __syncthreads();
    {
        float4 gg = ((const float4*)ls_g)[lane];
        float4 bb = ((const float4*)ls_b)[lane];
        #pragma unroll
        for (int p = 0; p < 2; p++) {
            int r = wid + p*16;
            float4 v = *(float4*)&Hs[r*128 + lane*4];
            float s = v.x + v.y + v.z + v.w;
            #pragma unroll
            for (int o = 16; o; o >>= 1) s += __shfl_xor_sync(0xffffffffu, s, o);
            float mu = s * (1.0f/128.0f);
            float dx = v.x-mu, dy = v.y-mu, dz = v.z-mu, dw = v.w-mu;
            float q = dx*dx + dy*dy + dz*dz + dw*dw;
            #pragma unroll
            for (int o = 16; o; o >>= 1) q += __shfl_xor_sync(0xffffffffu, q, o);
            float rs = rsqrtf(q * (1.0f/128.0f) + EPSLN);
            XN[r*68 + lane*2]   = pk2(dx*rs*gg.x + bb.x, dy*rs*gg.y + bb.y);
            XN[r*68 + lane*2+1] = pk2(dz*rs*gg.z + bb.z, dw*rs*gg.w + bb.w);
            HB[r*68 + lane*2]   = pk2(v.x, v.y);
            HB[r*68 + lane*2+1] = pk2(v.z, v.w);
        }
    }

    #pragma unroll 1
    for (int u = 0; u < 10; u++) {
        int ubuf = MA_W0 + (u & 1)*UNIT_BYTES;
        int aOff = (u == 0) ? MA_XN : (u == 1) ? MA_T1 : MA_HB;
        float c[2][4] = {};
        CPA_WAIT1(); __syncthreads();
        cmpW5(c, smB, ubuf,              aOff, 68, 0,  tid);
        cmpW5(c, smB, ubuf + WBUF_BYTES, aOff, 68, 32, tid);
        if (u == 0) {
            #pragma unroll
            for (int nt = 0; nt < 2; nt++) {
                int n0 = warp_n8*16 + nt*8 + 2*q4;
                float2 bv = *(const float2*)&bs1[n0];
                T1[row0*68 + (n0>>1)] =
                    pk2(fmaxf(c[nt][0]+bv.x,0.f), fmaxf(c[nt][1]+bv.y,0.f));
                T1[row1*68 + (n0>>1)] =
                    pk2(fmaxf(c[nt][2]+bv.x,0.f), fmaxf(c[nt][3]+bv.y,0.f));
            }
        } else if (u == 1) {
            #pragma unroll
            for (int nt = 0; nt < 2; nt++) {
                int n0 = warp_n8*16 + nt*8 + 2*q4;
                float2 bv = *(const float2*)&bs2[n0];
                float2 h0 = *(float2*)&Hs[row0*128 + n0];
                float2 h1 = *(float2*)&Hs[row1*128 + n0];
                *(float2*)&HDS[(size_t)(rowBase+row0)*128 + n0] =
                    make_float2(c[nt][0]+bv.x+h0.x, c[nt][1]+bv.y+h0.y);
                *(float2*)&HDS[(size_t)(rowBase+row1)*128 + n0] =
                    make_float2(c[nt][2]+bv.x+h1.x, c[nt][3]+bv.y+h1.y);
            }
        } else {
            int w1u = u - 2;
            int tau = w1u >> 1, half = w1u & 1;
            uint32_t* ob = (uint32_t*)((half ? Bb : Ab) +
                            ((size_t)tau*ROWS + rowBase)*128);
            #pragma unroll
            for (int nt = 0; nt < 2; nt++) {
                int n0 = warp_n8*16 + nt*8 + 2*q4;
                float2 bv = half ? make_float2(0.f,0.f)
                                 : *(const float2*)&bi1[tau*128 + n0];
                ob[row0*64 + (n0>>1)] = pk2(c[nt][0]+bv.x, c[nt][1]+bv.y);
                ob[row1*64 + (n0>>1)] = pk2(c[nt][2]+bv.x, c[nt][3]+bv.y);
            }
        }
        __syncthreads();
        if (u + 2 < 10) {
            prefW5(smB + ubuf,              ma_unit(u+2),        tid);
            prefW5(smB + ubuf + WBUF_BYTES, ma_unit(u+2) + 4096, tid);
        }
        CPA_COMMIT();
    }
}

// ---------------- HMMA fused inter kernel (256 thr, unchanged from R15) -----
#define WSTR 68
#define SM_AS   0
#define SM_BS   17408
#define SM_W2   34816
#define SM_WM   69632
#define SM_BI2  86016
#define SM_TOT  86528

__global__ void __launch_bounds__(256, 1) inter_hmma_kernel(
    const __nv_bfloat16* __restrict__ gAb, const __nv_bfloat16* __restrict__ gBb,
    const float* __restrict__ bi2,
    __nv_bfloat16* __restrict__ gSb, float* __restrict__ gW)
{
    extern __shared__ char sm[];
    uint32_t* Asm  = (uint32_t*)(sm + SM_AS);
    uint32_t* Bsm  = (uint32_t*)(sm + SM_BS);
    uint32_t* W2s  = (uint32_t*)(sm + SM_W2);
    float* Wmat = (float*)(sm + SM_WM);
    float* bi2s = (float*)(sm + SM_BI2);

    int tid = threadIdx.x, lane = tid & 31, wid = tid >> 5;
    int b = blockIdx.x, tau = blockIdx.y;
    int g = lane >> 2, q4 = lane & 3;
    int warp_p  = wid >> 2;
    int warp_j  = (wid >> 1) & 1;
    int warp_nh = wid & 1;
    int lA_row = lane & 15, lA_kw = (lane >> 4) << 2;
    int lB_row = (lane & 7) + ((lane >> 4) << 3);
    int lB_kw  = ((lane >> 3) & 1) << 2;
    uint32_t BsB = s2u(sm) + SM_BS, W2B = s2u(sm) + SM_W2;

    const uint4* Ag = (const uint4*)(gAb + ((size_t)tau*ROWS + b*64)*128);
    const uint4* Bg = (const uint4*)(gBb + ((size_t)tau*ROWS + b*64)*128);
    #pragma unroll
    for (int l = 0; l < 4; l++) {
        int v = tid + l*256;
        int row = v >> 4, wq = v & 15;
        *(uint4*)&Asm[row*WSTR + wq*4] = Ag[row*16 + wq];
        *(uint4*)&Bsm[row*WSTR + wq*4] = Bg[row*16 + wq];
    }
    {
        const uint4* src = (const uint4*)(g_Wp + W_WI2F + tau*8192);
        #pragma unroll
        for (int l = 0; l < 8; l++) {
            int u = tid + l*256;
            int n = u >> 4, q = u & 15;
            *(uint4*)&W2s[n*WSTR + q*4] = src[u];
        }
    }
    {
        const float4* Wg4 = (const float4*)(g_Wm + (((size_t)tau*64 + b) << 12));
        #pragma unroll
        for (int l = 0; l < 4; l++)
            ((float4*)Wmat)[tid + l*256] = Wg4[tid + l*256];
    }
    if (tid < 128) bi2s[tid] = bi2[tau*128 + tid];
    __syncthreads();

    if (tid < 64) {
        float s = 0.f;
        #pragma unroll 8
        for (int i = 0; i < 64; i++) s += Wmat[i*64 + tid];
        gW[(size_t)(b*64 + tid)*4 + tau] = s;
    }

    float bi2v[8][2];
    #pragma unroll
    for (int nn = 0; nn < 8; nn++) {
        int n0 = warp_nh*64 + nn*8 + 2*q4;
        bi2v[nn][0] = bi2s[n0];
        bi2v[nn][1] = bi2s[n0 + 1];
    }

    float S[2][8][4] = {};

    for (int it = 0; it < 32; it++) {
        int i = 2*it + warp_p;
        float c[2][8][4] = {};
        #pragma unroll
        for (int kk = 0; kk < 8; kk++) {
            uint32_t aw0 = Asm[i*WSTR + kk*8 + q4];
            uint32_t aw1 = Asm[i*WSTR + kk*8 + 4 + q4];
            uint32_t wf[4][4];
            #pragma unroll
            for (int nf = 0; nf < 4; nf++)
                ldmx4(wf[nf], W2B + ((warp_nh*64 + nf*16 + lB_row)*WSTR
                                     + kk*8 + lB_kw)*4);
            #pragma unroll
            for (int mt = 0; mt < 2; mt++) {
                uint32_t xb[4], x[4];
                ldmx4(xb, BsB + ((warp_j*32 + mt*16 + lA_row)*WSTR
                                 + kk*8 + lA_kw)*4);
                x[0] = addrelu2(xb[0], aw0);
                x[1] = addrelu2(xb[1], aw0);
                x[2] = addrelu2(xb[2], aw1);
                x[3] = addrelu2(xb[3], aw1);
                #pragma unroll
                for (int nf = 0; nf < 4; nf++) {
                    mma16816(c[mt][2*nf],   x, wf[nf][0], wf[nf][1]);
                    mma16816(c[mt][2*nf+1], x, wf[nf][2], wf[nf][3]);
                }
            }
        }
        #pragma unroll
        for (int mt = 0; mt < 2; mt++) {
            int jr = warp_j*32 + mt*16 + g;
            float w0 = Wmat[i*64 + jr];
            float w1 = Wmat[i*64 + jr + 8];
            #pragma unroll
            for (int nn = 0; nn < 8; nn++) {
                S[mt][nn][0] += w0*fmaxf(c[mt][nn][0] + bi2v[nn][0], 0.f);
                S[mt][nn][1] += w0*fmaxf(c[mt][nn][1] + bi2v[nn][1], 0.f);
                S[mt][nn][2] += w1*fmaxf(c[mt][nn][2] + bi2v[nn][0], 0.f);
                S[mt][nn][3] += w1*fmaxf(c[mt][nn][3] + bi2v[nn][1], 0.f);
            }
        }
    }

    float* Sout = (float*)(sm + SM_W2);
    __syncthreads();
    if (warp_p == 0) {
        #pragma unroll
        for (int mt = 0; mt < 2; mt++) {
            int j = warp_j*32 + mt*16 + g;
            #pragma unroll
            for (int nn = 0; nn < 8; nn++) {
                int n = warp_nh*64 + nn*8 + 2*q4;
                *(float2*)&Sout[j*132 + n] =
                    make_float2(S[mt][nn][0], S[mt][nn][1]);
                *(float2*)&Sout[(j+8)*132 + n] =
                    make_float2(S[mt][nn][2], S[mt][nn][3]);
            }
        }
    }
    __syncthreads();
    if (warp_p == 1) {
        #pragma unroll
        for (int mt = 0; mt < 2; mt++) {
            int j = warp_j*32 + mt*16 + g;
            #pragma unroll
            for (int nn = 0; nn < 8; nn++) {
                int n = warp_nh*64 + nn*8 + 2*q4;
                float2 v0 = *(float2*)&Sout[j*132 + n];
                v0.x += S[mt][nn][0]; v0.y += S[mt][nn][1];
                *(float2*)&Sout[j*132 + n] = v0;
                float2 v1 = *(float2*)&Sout[(j+8)*132 + n];
                v1.x += S[mt][nn][2]; v1.y += S[mt][nn][3];
                *(float2*)&Sout[(j+8)*132 + n] = v1;
            }
        }
    }
    __syncthreads();
    for (int q = tid; q < 2048; q += 256) {
        int j = q >> 5, w = q & 31;
        float4 v = *(float4*)&Sout[j*132 + w*4];
        uint2 u = make_uint2(pk2(v.x, v.y), pk2(v.z, v.w));
        *(uint2*)&gSb[(size_t)(b*64 + j)*512 + tau*128 + w*4] = u;
    }
}

// ---------------- megaB: wi3 + LN256 + update MLP (512 thr) -----------------
#define MB_AS0  0
#define MB_DI   18432
#define MB_CN   35328
#define MB_T1   52224
#define MB_W0   60928
#define MB_TOT  134656

__device__ __forceinline__ const uint32_t* mb_unit(int u){
    if (u < 4)  return g_Wp + W_WI3 + u*8192;
    if (u < 6)  return g_Wp + W_WU1 + (u-4)*8192;
    return g_Wp + W_WU2;
}

__global__ void __launch_bounds__(512) megaB_kernel(
    const __nv_bfloat16* __restrict__ Sb, const float* __restrict__ Wq,
    const float* __restrict__ bi3, const float* __restrict__ HDS,
    const float* __restrict__ lu_g, const float* __restrict__ lu_b,
    const float* __restrict__ bu1, const float* __restrict__ bu2,
    const float* __restrict__ hResid, float* __restrict__ hOut)
{
    extern __shared__ char sm[];
    float*    DIs = (float*)(sm + MB_DI);
    uint32_t* CN = (uint32_t*)(sm + MB_CN);
    uint32_t* T1 = (uint32_t*)(sm + MB_T1);
    uint32_t smB = s2u(sm);
    int tid = threadIdx.x, lane = tid & 31, wid = tid >> 5;
    int rowBase = blockIdx.x * 32;
    int g = lane >> 2, q4 = lane & 3;
    int warp_m = wid >> 3, warp_n8 = wid & 7;
    int row0 = warp_m*16 + g, row1 = row0 + 8;

    prefW5(smB + MB_W0,              mb_unit(0),        tid);
    prefW5(smB + MB_W0 + WBUF_BYTES, mb_unit(0) + 4096, tid);
    prefS5(smB + MB_AS0,        Sb, rowBase, 0, tid);
    prefS5(smB + MB_AS0 + 4608, Sb, rowBase, 1, tid);
    CPA_COMMIT();
    prefW5(smB + MB_W0 + UNIT_BYTES,              mb_unit(1),        tid);
    prefW5(smB + MB_W0 + UNIT_BYTES + WBUF_BYTES, mb_unit(1) + 4096, tid);
    prefS5(smB + MB_AS0 + 9216,  Sb, rowBase, 2, tid);
    prefS5(smB + MB_AS0 + 13824, Sb, rowBase, 3, tid);
    CPA_COMMIT();

    float c[2][4] = {};
    #pragma unroll 1
    for (int u = 0; u < 7; u++) {
        int ubuf = MB_W0 + (u & 1)*UNIT_BYTES;
        CPA_WAIT1(); __syncthreads();
        if (u < 4) {
            int asb = MB_AS0 + (u & 1)*9216;
            cmpW5(c, smB, ubuf,              asb,        36, 0, tid);
            cmpW5(c, smB, ubuf + WBUF_BYTES, asb + 4608, 36, 0, tid);
        } else if (u < 6) {
            int aCh = (u - 4)*64;
            cmpW5(c, smB, ubuf,              MB_CN, 132, aCh,      tid);
            cmpW5(c, smB, ubuf + WBUF_BYTES, MB_CN, 132, aCh + 32, tid);
        } else {
            cmpW5(c, smB, ubuf,              MB_T1, 68, 0,  tid);
            cmpW5(c, smB, ubuf + WBUF_BYTES, MB_T1, 68, 32, tid);
        }

        if (u == 3) {
            float4 wa = *(const float4*)&Wq[(size_t)(rowBase+row0)*4];
            float4 wb = *(const float4*)&Wq[(size_t)(rowBase+row1)*4];
            #pragma unroll
            for (int nt = 0; nt < 2; nt++) {
                int n0 = warp_n8*16 + nt*8 + 2*q4;
                float2 v0 = make_float2(c[nt][0], c[nt][1]);
                float2 v1 = make_float2(c[nt][2], c[nt][3]);
                #pragma unroll
                for (int t = 0; t < 4; t++) {
                    float wta = (t==0)?wa.x:(t==1)?wa.y:(t==2)?wa.z:wa.w;
                    float wtb = (t==0)?wb.x:(t==1)?wb.y:(t==2)?wb.z:wb.w;
                    float2 rb = *(const float2*)&bi3[t*128 + n0];
                    v0.x += wta*rb.x; v0.y += wta*rb.y;
                    v1.x += wtb*rb.x; v1.y += wtb*rb.y;
                }
                *(float2*)&DIs[row0*132 + n0] = v0;
                *(float2*)&DIs[row1*132 + n0] = v1;
            }
            #pragma unroll
            for (int a = 0; a < 2; a++)
                #pragma unroll
                for (int d = 0; d < 4; d++) c[a][d] = 0.f;
            __syncthreads();
            float4 g0 = ((const float4*)lu_g)[lane];
            float4 g1 = ((const float4*)lu_g)[32 + lane];
            float4 c0 = ((const float4*)lu_b)[lane];
            float4 c1 = ((const float4*)lu_b)[32 + lane];
            #pragma unroll
            for (int p = 0; p < 2; p++) {
                int r = wid + p*16;
                float4 v0 = *(const float4*)&HDS[(size_t)(rowBase+r)*128 + lane*4];
                float4 v1 = *(float4*)&DIs[r*132 + lane*4];
                float s = v0.x+v0.y+v0.z+v0.w + v1.x+v1.y+v1.z+v1.w;
                #pragma unroll
                for (int o = 16; o; o >>= 1) s += __shfl_xor_sync(0xffffffffu, s, o);
                float mu = s * (1.0f/256.0f);
                float a0=v0.x-mu, a1=v0.y-mu, a2=v0.z-mu, a3=v0.w-mu;
                float b0=v1.x-mu, b1=v1.y-mu, b2=v1.z-mu, b3=v1.w-mu;
                float q = a0*a0+a1*a1+a2*a2+a3*a3 + b0*b0+b1*b1+b2*b2+b3*b3;
                #pragma unroll
                for (int o = 16; o; o >>= 1) q += __shfl_xor_sync(0xffffffffu, q, o);
                float rs = rsqrtf(q * (1.0f/256.0f) + EPSLN);
                CN[r*132 + lane*2]        = pk2(a0*rs*g0.x + c0.x, a1*rs*g0.y + c0.y);
                CN[r*132 + lane*2 + 1]    = pk2(a2*rs*g0.z + c0.z, a3*rs*g0.w + c0.w);
                CN[r*132 + 64 + lane*2]   = pk2(b0*rs*g1.x + c1.x, b1*rs*g1.y + c1.y);
                CN[r*132 + 64 + lane*2+1] = pk2(b2*rs*g1.z + c1.z, b3*rs*g1.w + c1.w);
            }
        } else if (u == 5) {
            #pragma unroll
            for (int nt = 0; nt < 2; nt++) {
                int n0 = warp_n8*16 + nt*8 + 2*q4;
                float2 bv = *(const float2*)&bu1[n0];
                T1[row0*68 + (n0>>1)] =
                    pk2(fmaxf(c[nt][0]+bv.x,0.f), fmaxf(c[nt][1]+bv.y,0.f));
                T1[row1*68 + (n0>>1)] =
                    pk2(fmaxf(c[nt][2]+bv.x,0.f), fmaxf(c[nt][3]+bv.y,0.f));
            }
            #pragma unroll
            for (int a = 0; a < 2; a++)
                #pragma unroll
                for (int d = 0; d < 4; d++) c[a][d] = 0.f;
        } else if (u == 6) {
            #pragma unroll
            for (int nt = 0; nt < 2; nt++) {
                int n0 = warp_n8*16 + nt*8 + 2*q4;
                float2 bv = *(const float2*)&bu2[n0];
                float2 h0 = *(const float2*)&hResid[(size_t)(rowBase+row0)*128 + n0];
                float2 h1 = *(const float2*)&hResid[(size_t)(rowBase+row1)*128 + n0];
                *(float2*)&hOut[(size_t)(rowBase+row0)*128 + n0] =
                    make_float2(c[nt][0]+bv.x+h0.x, c[nt][1]+bv.y+h0.y);
                *(float2*)&hOut[(size_t)(rowBase+row1)*128 + n0] =
                    make_float2(c[nt][2]+bv.x+h1.x, c[nt][3]+bv.y+h1.y);
            }
        }
        __syncthreads();
        if (u + 2 < 7) {
            int nu = u + 2;
            prefW5(smB + ubuf,              mb_unit(nu),        tid);
            prefW5(smB + ubuf + WBUF_BYTES, mb_unit(nu) + 4096, tid);
            if (nu < 4) {
                prefS5(smB + MB_AS0 + (u & 1)*9216,        Sb, rowBase, nu*2,   tid);
                prefS5(smB + MB_AS0 + (u & 1)*9216 + 4608, Sb, rowBase, nu*2+1, tid);
            }
        }
        CPA_COMMIT();
    }
}

// ---------------- megaBA: fused megaB(it0) + megaA(it1) (512 thr) -----------
#define BA_W0   0
#define BA_AS   73728
#define BA_DI   92160
#define BA_CN   109056
#define BA_T1B  125952
#define BA_HS   134656
#define BA_XN   151040
#define BA_HB   159744
#define BA_T1A  168448
#define BA_TOT  177152

__device__ __forceinline__ const uint32_t* ba_unit(int g){
    if (g < 4)  return g_Wp + W_WI3 + g*8192;
    if (g < 6)  return g_Wp + W_WU1 + (g-4)*8192;
    if (g == 6) return g_Wp + W_WU2;
    if (g == 7) return g_Wp + W_WS1;
    if (g == 8) return g_Wp + W_WS2;
    return g_Wp + W_WI1 + (g-9)*8192;
}

__global__ void __launch_bounds__(512) megaBA_kernel(
    const __nv_bfloat16* __restrict__ Sb, const float* __restrict__ Wq,
    const float* __restrict__ bi3, const float* __restrict__ HDS,
    const float* __restrict__ lu_g, const float* __restrict__ lu_b,
    const float* __restrict__ bu1, const float* __restrict__ bu2,
    const float* __restrict__ hResid, float* __restrict__ hOut,
    const float* __restrict__ ls_g, const float* __restrict__ ls_b,
    const float* __restrict__ bs1, const float* __restrict__ bs2,
    const float* __restrict__ bi1, float* __restrict__ HDSo,
    __nv_bfloat16* __restrict__ Ab, __nv_bfloat16* __restrict__ Bb)
{
    extern __shared__ char sm[];
    float*    DIs = (float*)(sm + BA_DI);
    uint32_t* CN  = (uint32_t*)(sm + BA_CN);
    uint32_t* T1B = (uint32_t*)(sm + BA_T1B);
    float*    Hs  = (float*)(sm + BA_HS);
    uint32_t* XN  = (uint32_t*)(sm + BA_XN);
    uint32_t* HB  = (uint32_t*)(sm + BA_HB);
    uint32_t* T1A = (uint32_t*)(sm + BA_T1A);
    uint32_t smB = s2u(sm);
    int tid = threadIdx.x, lane = tid & 31, wid = tid >> 5;
    int rowBase = blockIdx.x * 32;
    int g = lane >> 2, q4 = lane & 3;
    int warp_m = wid >> 3, warp_n8 = wid & 7;
    int row0 = warp_m*16 + g, row1 = row0 + 8;

    prefW5(smB + BA_W0,              ba_unit(0),        tid);
    prefW5(smB + BA_W0 + WBUF_BYTES, ba_unit(0) + 4096, tid);
    prefS5(smB + BA_AS,        Sb, rowBase, 0, tid);
    prefS5(smB + BA_AS + 4608, Sb, rowBase, 1, tid);
    CPA_COMMIT();
    prefW5(smB + BA_W0 + UNIT_BYTES,              ba_unit(1),        tid);
    prefW5(smB + BA_W0 + UNIT_BYTES + WBUF_BYTES, ba_unit(1) + 4096, tid);
    prefS5(smB + BA_AS + 9216,  Sb, rowBase, 2, tid);
    prefS5(smB + BA_AS + 13824, Sb, rowBase, 3, tid);
    CPA_COMMIT();

    float c[2][4] = {};
    #pragma unroll 1
    for (int u = 0; u < 17; u++) {
        int ubuf = BA_W0 + (u & 1)*UNIT_BYTES;
        CPA_WAIT1(); __syncthreads();
        if (u < 4) {
            int asb = BA_AS + (u & 1)*9216;
            cmpW5(c, smB, ubuf,              asb,        36, 0, tid);
            cmpW5(c, smB, ubuf + WBUF_BYTES, asb + 4608, 36, 0, tid);
        } else if (u < 6) {
            int aCh = (u - 4)*64;
            cmpW5(c, smB, ubuf,              BA_CN, 132, aCh,      tid);
            cmpW5(c, smB, ubuf + WBUF_BYTES, BA_CN, 132, aCh + 32, tid);
        } else if (u == 6) {
            cmpW5(c, smB, ubuf,              BA_T1B, 68, 0,  tid);
            cmpW5(c, smB, ubuf + WBUF_BYTES, BA_T1B, 68, 32, tid);
        } else if (u == 7) {
            cmpW5(c, smB, ubuf,              BA_XN, 68, 0,  tid);
            cmpW5(c, smB, ubuf + WBUF_BYTES, BA_XN, 68, 32, tid);
        } else if (u == 8) {
            cmpW5(c, smB, ubuf,              BA_T1A, 68, 0,  tid);
            cmpW5(c, smB, ubuf + WBUF_BYTES, BA_T1A, 68, 32, tid);
        } else {
            cmpW5(c, smB, ubuf,              BA_HB, 68, 0,  tid);
            cmpW5(c, smB, ubuf + WBUF_BYTES, BA_HB, 68, 32, tid);
        }

        if (u == 3) {
            float4 wa = *(const float4*)&Wq[(size_t)(rowBase+row0)*4];
            float4 wb = *(const float4*)&Wq[(size_t)(rowBase+row1)*4];
            #pragma unroll
            for (int nt = 0; nt < 2; nt++) {
                int n0 = warp_n8*16 + nt*8 + 2*q4;
                float2 v0 = make_float2(c[nt][0], c[nt][1]);
                float2 v1 = make_float2(c[nt][2], c[nt][3]);
                #pragma unroll
                for (int t = 0; t < 4; t++) {
                    float wta = (t==0)?wa.x:(t==1)?wa.y:(t==2)?wa.z:wa.w;
                    float wtb = (t==0)?wb.x:(t==1)?wb.y:(t==2)?wb.z:wb.w;
                    float2 rb = *(const float2*)&bi3[t*128 + n0];
                    v0.x += wta*rb.x; v0.y += wta*rb.y;
                    v1.x += wtb*rb.x; v1.y += wtb*rb.y;
                }
                *(float2*)&DIs[row0*132 + n0] = v0;
                *(float2*)&DIs[row1*132 + n0] = v1;
            }
            #pragma unroll
            for (int a = 0; a < 2; a++)
                #pragma unroll
                for (int d = 0; d < 4; d++) c[a][d] = 0.f;
            __syncthreads();
            float4 g0 = ((const float4*)lu_g)[lane];
            float4 g1 = ((const float4*)lu_g)[32 + lane];
            float4 c0 = ((const float4*)lu_b)[lane];
            float4 c1 = ((const float4*)lu_b)[32 + lane];
            #pragma unroll
            for (int p = 0; p < 2; p++) {
                int r = wid + p*16;
                float4 v0 = *(const float4*)&HDS[(size_t)(rowBase+r)*128 + lane*4];
                float4 v1 = *(float4*)&DIs[r*132 + lane*4];
                float s = v0.x+v0.y+v0.z+v0.w + v1.x+v1.y+v1.z+v1.w;
                #pragma unroll
                for (int o = 16; o; o >>= 1) s += __shfl_xor_sync(0xffffffffu, s, o);
                float mu = s * (1.0f/256.0f);
                float a0=v0.x-mu, a1=v0.y-mu, a2=v0.z-mu, a3=v0.w-mu;
                float b0=v1.x-mu, b1=v1.y-mu, b2=v1.z-mu, b3=v1.w-mu;
                float q = a0*a0+a1*a1+a2*a2+a3*a3 + b0*b0+b1*b1+b2*b2+b3*b3;
                #pragma unroll
                for (int o = 16; o; o >>= 1) q += __shfl_xor_sync(0xffffffffu, q, o);
                float rs = rsqrtf(q * (1.0f/256.0f) + EPSLN);
                CN[r*132 + lane*2]        = pk2(a0*rs*g0.x + c0.x, a1*rs*g0.y + c0.y);
                CN[r*132 + lane*2 + 1]    = pk2(a2*rs*g0.z + c0.z, a3*rs*g0.w + c0.w);
                CN[r*132 + 64 + lane*2]   = pk2(b0*rs*g1.x + c1.x, b1*rs*g1.y + c1.y);
                CN[r*132 + 64 + lane*2+1] = pk2(b2*rs*g1.z + c1.z, b3*rs*g1.w + c1.w);
            }
        } else if (u == 5) {
            #pragma unroll
            for (int nt = 0; nt < 2; nt++) {
                int n0 = warp_n8*16 + nt*8 + 2*q4;
                float2 bv = *(const float2*)&bu1[n0];
                T1B[row0*68 + (n0>>1)] =
                    pk2(fmaxf(c[nt][0]+bv.x,0.f), fmaxf(c[nt][1]+bv.y,0.f));
                T1B[row1*68 + (n0>>1)] =
                    pk2(fmaxf(c[nt][2]+bv.x,0.f), fmaxf(c[nt][3]+bv.y,0.f));
            }
            #pragma unroll
            for (int a = 0; a < 2; a++)
                #pragma unroll
                for (int d = 0; d < 4; d++) c[a][d] = 0.f;
        } else if (u == 6) {
            #pragma unroll
            for (int nt = 0; nt < 2; nt++) {
                int n0 = warp_n8*16 + nt*8 + 2*q4;
                float2 bv = *(const float2*)&bu2[n0];
                float2 h0 = *(const float2*)&hResid[(size_t)(rowBase+row0)*128 + n0];
                float2 h1 = *(const float2*)&hResid[(size_t)(rowBase+row1)*128 + n0];
                float2 o0 = make_float2(c[nt][0]+bv.x+h0.x, c[nt][1]+bv.y+h0.y);
                float2 o1 = make_float2(c[nt][2]+bv.x+h1.x, c[nt][3]+bv.y+h1.y);
                *(float2*)&hOut[(size_t)(rowBase+row0)*128 + n0] = o0;
                *(float2*)&hOut[(size_t)(rowBase+row1)*128 + n0] = o1;
                *(float2*)&Hs[row0*128 + n0] = o0;
                *(float2*)&Hs[row1*128 + n0] = o1;
            }
            #pragma unroll
            for (int a = 0; a < 2; a++)
                #pragma unroll
                for (int d = 0; d < 4; d++) c[a][d] = 0.f;
            __syncthreads();
            float4 gg = ((const float4*)ls_g)[lane];
            float4 bb = ((const float4*)ls_b)[lane];
            #pragma unroll
            for (int p = 0; p < 2; p++) {
                int r = wid + p*16;
                float4 v = *(float4*)&Hs[r*128 + lane*4];
                float s = v.x + v.y + v.z + v.w;
                #pragma unroll
                for (int o = 16; o; o >>= 1) s += __shfl_xor_sync(0xffffffffu, s, o);
                float mu = s * (1.0f/128.0f);
                float dx = v.x-mu, dy = v.y-mu, dz = v.z-mu, dw = v.w-mu;
                float q = dx*dx + dy*dy + dz*dz + dw*dw;
                #pragma unroll
                for (int o = 16; o; o >>= 1) q += __shfl_xor_sync(0xffffffffu, q, o);
                float rs = rsqrtf(q * (1.0f/128.0f) + EPSLN);
                XN[r*68 + lane*2]   = pk2(dx*rs*gg.x + bb.x, dy*rs*gg.y + bb.y);
                XN[r*68 + lane*2+1] = pk2(dz*rs*gg.z + bb.z, dw*rs*gg.w + bb.w);
                HB[r*68 + lane*2]   = pk2(v.x, v.y);
                HB[r*68 + lane*2+1] = pk2(v.z, v.w);
            }
        } else if (u == 7) {
            #pragma unroll
            for (int nt = 0; nt < 2; nt++) {
                int n0 = warp_n8*16 + nt*8 + 2*q4;
                float2 bv = *(const float2*)&bs1[n0];
                T1A[row0*68 + (n0>>1)] =
                    pk2(fmaxf(c[nt][0]+bv.x,0.f), fmaxf(c[nt][1]+bv.y,0.f));
                T1A[row1*68 + (n0>>1)] =
                    pk2(fmaxf(c[nt][2]+bv.x,0.f), fmaxf(c[nt][3]+bv.y,0.f));
            }
            #pragma unroll
            for (int a = 0; a < 2; a++)
                #pragma unroll
                for (int d = 0; d < 4; d++) c[a][d] = 0.f;
        } else if (u == 8) {
            #pragma unroll
            for (int nt = 0; nt < 2; nt++) {
                int n0 = warp_n8*16 + nt*8 + 2*q4;
                float2 bv = *(const float2*)&bs2[n0];
                float2 h0 = *(float2*)&Hs[row0*128 + n0];
                float2 h1 = *(float2*)&Hs[row1*128 + n0];
                *(float2*)&HDSo[(size_t)(rowBase+row0)*128 + n0] =
                    make_float2(c[nt][0]+bv.x+h0.x, c[nt][1]+bv.y+h0.y);
                *(float2*)&HDSo[(size_t)(rowBase+row1)*128 + n0] =
                    make_float2(c[nt][2]+bv.x+h1.x, c[nt][3]+bv.y+h1.y);
            }
            #pragma unroll
            for (int a = 0; a < 2; a++)
                #pragma unroll
                for (int d = 0; d < 4; d++) c[a][d] = 0.f;
        } else if (u >= 9) {
            int w1u = u - 9;
            int tau = w1u >> 1, half = w1u & 1;
            uint32_t* ob = (uint32_t*)((half ? Bb : Ab) +
                            ((size_t)tau*ROWS + rowBase)*128);
            #pragma unroll
            for (int nt = 0; nt < 2; nt++) {
                int n0 = warp_n8*16 + nt*8 + 2*q4;
                float2 bv = half ? make_float2(0.f,0.f)
                                 : *(const float2*)&bi1[tau*128 + n0];
                ob[row0*64 + (n0>>1)] = pk2(c[nt][0]+bv.x, c[nt][1]+bv.y);
                ob[row1*64 + (n0>>1)] = pk2(c[nt][2]+bv.x, c[nt][3]+bv.y);
            }
            #pragma unroll
            for (int a = 0; a < 2; a++)
                #pragma unroll
                for (int d = 0; d < 4; d++) c[a][d] = 0.f;
        }
        __syncthreads();
        int t = u + 2;
        if (t < 17) {
            prefW5(smB + ubuf,              ba_unit(t),        tid);
            prefW5(smB + ubuf + WBUF_BYTES, ba_unit(t) + 4096, tid);
            if (t < 4) {
                prefS5(smB + BA_AS + (u & 1)*9216,        Sb, rowBase, t*2,   tid);
                prefS5(smB + BA_AS + (u & 1)*9216 + 4608, Sb, rowBase, t*2+1, tid);
            }
        }
        CPA_COMMIT();
    }
}

// ---------------- host orchestration ----------------
extern "C" void kernel_launch(void* const* d_in, const int* in_sizes, int n_in,
                              void* d_out, int out_size)
{
    const float* slots = (const float*)d_in[0];
    const float* ep    = (const float*)d_in[1];
    const float* et    = (const float*)d_in[2];
    const float* ls_g  = (const float*)d_in[3];
    const float* ls_b  = (const float*)d_in[4];
    const float* ws1   = (const float*)d_in[5];
    const float* bs1   = (const float*)d_in[6];
    const float* ws2   = (const float*)d_in[7];
    const float* bs2   = (const float*)d_in[8];
    const float* wi1   = (const float*)d_in[9];
    const float* bi1   = (const float*)d_in[10];
    const float* wi2   = (const float*)d_in[11];
    const float* bi2   = (const float*)d_in[12];
    const float* wi3   = (const float*)d_in[13];
    const float* bi3   = (const float*)d_in[14];
    const float* lu_g  = (const float*)d_in[15];
    const float* lu_b  = (const float*)d_in[16];
    const float* wu1   = (const float*)d_in[17];
    const float* bu1   = (const float*)d_in[18];
    const float* wu2   = (const float*)d_in[19];
    const float* bu2   = (const float*)d_in[20];
    float* out = (float*)d_out;

    float *HDS, *H, *W;
    __nv_bfloat16 *Ab, *Bb, *Sb;
    cudaGetSymbolAddress((void**)&HDS, g_HDS);
    cudaGetSymbolAddress((void**)&H,   g_H);
    cudaGetSymbolAddress((void**)&W,   g_W);
    cudaGetSymbolAddress((void**)&Ab,  g_Ab);
    cudaGetSymbolAddress((void**)&Bb,  g_Bb);
    cudaGetSymbolAddress((void**)&Sb,  g_Sb);

    cudaFuncSetAttribute(megaA_kernel,
        cudaFuncAttributeMaxDynamicSharedMemorySize, MA_TOT);
    cudaFuncSetAttribute(megaB_kernel,
        cudaFuncAttributeMaxDynamicSharedMemorySize, MB_TOT);
    cudaFuncSetAttribute(megaBA_kernel,
        cudaFuncAttributeMaxDynamicSharedMemorySize, BA_TOT);
    cudaFuncSetAttribute(inter_hmma_kernel,
        cudaFuncAttributeMaxDynamicSharedMemorySize, SM_TOT);

    prep_weights<<<(PREP_TOTAL+255)/256, 256>>>(ws1, ws2, wu2, wi3, wu1,
                                                wi1, wi2, ep, et);

    // iteration 0
    megaA_kernel<<<128, 512, MA_TOT>>>(slots, ls_g, ls_b, bs1, bs2, bi1,
                                       HDS, Ab, Bb);
    inter_hmma_kernel<<<dim3(BB, TT), 256, SM_TOT>>>(Ab, Bb, bi2, Sb, W);
    // fused: megaB(it0) -> H ; megaA(it1) -> HDS, Ab, Bb
    megaBA_kernel<<<128, 512, BA_TOT>>>(Sb, W, bi3, HDS, lu_g, lu_b,
                                        bu1, bu2, slots, H,
                                        ls_g, ls_b, bs1, bs2, bi1,
                                        HDS, Ab, Bb);
    // iteration 1
    inter_hmma_kernel<<<dim3(BB, TT), 256, SM_TOT>>>(Ab, Bb, bi2, Sb, W);
    megaB_kernel<<<128, 512, MB_TOT>>>(Sb, W, bi3, HDS, lu_g, lu_b,
                                       bu1, bu2, H, out);
}

// round 17
// speedup vs baseline: 1.0183x; 1.0183x over previous
#include <cuda_runtime.h>
#include <cuda_bf16.h>
#include <cstdint>

// Problem constants
#define BB 64
#define KK 64
#define DD 128
#define HH 128
#define TT 4
#define ROWS (BB*KK)        // 4096
#define EPSLN 1e-5f

// ---------------- scratch (no allocations allowed) ----------------
__device__ __align__(16) float g_HDS[ROWS*DD];
__device__ __align__(16) float g_H  [ROWS*DD];
__device__ __align__(16) float g_W  [ROWS*TT];          // [row][tau]
__device__ __align__(16) float g_Wm [TT*BB*64*64];      // [tau][b][i][j] = ep*et
__device__ __align__(16) __nv_bfloat16 g_Ab [TT*ROWS*HH];
__device__ __align__(16) __nv_bfloat16 g_Bb [TT*ROWS*HH];
__device__ __align__(16) __nv_bfloat16 g_Sb [ROWS*TT*HH];   // [row][tau*128+n]

// prepped weights: bf16, [n][k-pair] chunked (4096 words per 64-k chunk)
#define W_WS1   0
#define W_WS2   8192
#define W_WU2   16384
#define W_WI3   24576
#define W_WU1   57344
#define W_WI1   73728
#define W_WI2F  139264
#define W_TOTAL 172032
#define PREP_TOTAL (W_TOTAL + TT*BB*64*64)
__device__ __align__(16) uint32_t g_Wp[W_TOTAL];

// ---------------- helpers ----------------
__device__ __forceinline__ uint32_t pk2(float lo, float hi){
    __nv_bfloat162 v = __floats2bfloat162_rn(lo, hi);
    return *(uint32_t*)&v;
}
__device__ __forceinline__ uint32_t addrelu2(uint32_t a, uint32_t b){
    __nv_bfloat162 av = *(__nv_bfloat162*)&a;
    __nv_bfloat162 bv = *(__nv_bfloat162*)&b;
    __nv_bfloat162 z  = __float2bfloat162_rn(0.f);
    __nv_bfloat162 r  = __hmax2(__hadd2(av, bv), z);
    return *(uint32_t*)&r;
}
__device__ __forceinline__ void mma16816(float c[4], const uint32_t a[4],
                                         uint32_t b0, uint32_t b1){
    asm volatile(
        "mma.sync.aligned.m16n8k16.row.col.f32.bf16.bf16.f32 "
        "{%0,%1,%2,%3}, {%4,%5,%6,%7}, {%8,%9}, {%0,%1,%2,%3};\n"
        : "+f"(c[0]), "+f"(c[1]), "+f"(c[2]), "+f"(c[3])
        : "r"(a[0]), "r"(a[1]), "r"(a[2]), "r"(a[3]), "r"(b0), "r"(b1));
}
__device__ __forceinline__ void ldmx4(uint32_t r[4], uint32_t a){
    asm volatile("ldmatrix.sync.aligned.m8n8.x4.shared.b16 {%0,%1,%2,%3}, [%4];"
        : "=r"(r[0]), "=r"(r[1]), "=r"(r[2]), "=r"(r[3]) : "r"(a));
}
__device__ __forceinline__ uint32_t s2u(const void* p){
    return (uint32_t)__cvta_generic_to_shared((void*)p);
}
__device__ __forceinline__ void cpa16(uint32_t dst, const void* src){
    asm volatile("cp.async.cg.shared.global [%0], [%1], 16;"
                 :: "r"(dst), "l"(src) : "memory");
}
#define CPA_COMMIT() asm volatile("cp.async.commit_group;" ::: "memory")
#define CPA_WAIT1()  asm volatile("cp.async.wait_group 1;" ::: "memory")

// ---------------- weight prep + pair-weight precompute ----------------
__global__ void __launch_bounds__(256) prep_weights(
    const float* __restrict__ ws1, const float* __restrict__ ws2,
    const float* __restrict__ wu2, const float* __restrict__ wi3,
    const float* __restrict__ wu1, const float* __restrict__ wi1,
    const float* __restrict__ wi2,
    const float* __restrict__ ep,  const float* __restrict__ et)
{
    int idx = blockIdx.x*256 + threadIdx.x;
    if (idx >= PREP_TOTAL) return;
    if (idx >= W_TOTAL) {
        int m = idx - W_TOTAL;          // [tau][b][i][j]
        int j = m & 63, i = (m >> 6) & 63, b = (m >> 12) & 63, tau = m >> 18;
        size_t pid = ((size_t)b*64 + i)*64 + j;
        g_Wm[m] = ep[pid] * et[pid*4 + tau];
        return;
    }
    const float* src;
    int local;
    if (idx < W_WS2)       { src = ws1; local = idx - W_WS1; }
    else if (idx < W_WU2)  { src = ws2; local = idx - W_WS2; }
    else if (idx < W_WI3)  { src = wu2; local = idx - W_WU2; }
    else if (idx < W_WU1)  { src = wi3; local = idx - W_WI3; }
    else if (idx < W_WI1)  { src = wu1; local = idx - W_WU1; }
    else if (idx < W_WI2F) {
        int l = idx - W_WI1;
        int tau = l >> 14;
        src = wi1 + (size_t)tau*256*128;
        local = l & 16383;
    } else {
        int l = idx - W_WI2F;
        int tau = l >> 13;
        int r = l & 8191;
        int n = r >> 6, w = r & 63;
        const float* s = wi2 + (size_t)tau*16384;
        g_Wp[idx] = pk2(s[(size_t)(2*w)*128 + n], s[(size_t)(2*w+1)*128 + n]);
        return;
    }
    int c = local >> 12;
    int r = local & 4095;
    int n = r >> 5, w = r & 31;
    int k = c*64 + 2*w;
    g_Wp[idx] = pk2(src[(size_t)k*128 + n], src[(size_t)(k+1)*128 + n]);
}

// ---------------- pipelined GEMM primitives (32 rows x 128 n x 64 k) --------
#define GSTR 36
#define WBUF_BYTES 18432
#define UNIT_BYTES (2*WBUF_BYTES)

__device__ __forceinline__ void prefW(uint32_t dstBase,
                                      const uint32_t* __restrict__ Wg, int tid){
    #pragma unroll
    for (int l = 0; l < 4; l++) {
        int u = tid + l*256;
        int n = u >> 3, w0 = (u & 7)*4;
        cpa16(dstBase + (uint32_t)(n*GSTR + w0)*4, Wg + u*4);
    }
}
__device__ __forceinline__ void prefS(uint32_t dstBase,
                                      const __nv_bfloat16* __restrict__ Sb,
                                      int rowBase, int c8, int tid){
    int lr = tid >> 3, uu = tid & 7;
    cpa16(dstBase + (uint32_t)(lr*36 + uu*4)*4,
          (const uint4*)Sb + (size_t)(rowBase+lr)*64 + c8*8 + uu);
}
__device__ __forceinline__ void cmpW(
    float (&c)[4][4], uint32_t smB, int wtOff,
    int aOff, int astr, int aChunkOff, int tid)
{
    int lane = tid & 31, wid = tid >> 5;
    int warp_m = wid >> 2, warp_n = wid & 3;
    int lA_row = lane & 15, lA_kw = (lane >> 4) << 2;
    int lB_row = (lane & 7) + ((lane >> 4) << 3);
    int lB_kw  = ((lane >> 3) & 1) << 2;
    uint32_t AsB = smB + aOff, WtB = smB + (uint32_t)wtOff;
    #pragma unroll
    for (int kk = 0; kk < 4; kk++) {
        uint32_t wf0[4], wf1[4], a[4];
        ldmx4(wf0, WtB + ((warp_n*32 + lB_row)*GSTR + kk*8 + lB_kw)*4);
        ldmx4(wf1, WtB + ((warp_n*32 + 16 + lB_row)*GSTR + kk*8 + lB_kw)*4);
        ldmx4(a, AsB + ((warp_m*16 + lA_row)*astr + aChunkOff + kk*8 + lA_kw)*4);
        mma16816(c[0], a, wf0[0], wf0[1]);
        mma16816(c[1], a, wf0[2], wf0[3]);
        mma16816(c[2], a, wf1[0], wf1[1]);
        mma16816(c[3], a, wf1[2], wf1[3]);
    }
}

// ---------------- megaA: LN128 + self-MLP + wi1 (unit-batched, depth-2) -----
#define MA_HS   0
#define MA_XN   16384
#define MA_HB   25088
#define MA_T1   33792
#define MA_W0   42496
#define MA_TOT  116224

__device__ __forceinline__ const uint32_t* ma_unit(int u){
    if (u == 0) return g_Wp + W_WS1;
    if (u == 1) return g_Wp + W_WS2;
    return g_Wp + W_WI1 + (u-2)*8192;
}

__global__ void __launch_bounds__(256) megaA_kernel(
    const float* __restrict__ h,
    const float* __restrict__ ls_g, const float* __restrict__ ls_b,
    const float* __restrict__ bs1, const float* __restrict__ bs2,
    const float* __restrict__ bi1,
    float* __restrict__ HDS, __nv_bfloat16* __restrict__ Ab,
    __nv_bfloat16* __restrict__ Bb)
{
    extern __shared__ char sm[];
    float* Hs = (float*)(sm + MA_HS);
    uint32_t* XN = (uint32_t*)(sm + MA_XN);
    uint32_t* HB = (uint32_t*)(sm + MA_HB);
    uint32_t* T1 = (uint32_t*)(sm + MA_T1);
    uint32_t smB = s2u(sm);
    int tid = threadIdx.x, lane = tid & 31, wid = tid >> 5;
    int rowBase = blockIdx.x * 32;
    int g = lane >> 2, q4 = lane & 3;
    int warp_m = wid >> 2, warp_n = wid & 3;
    int row0 = warp_m*16 + g, row1 = row0 + 8;

    prefW(smB + MA_W0,              ma_unit(0),        tid);
    prefW(smB + MA_W0 + WBUF_BYTES, ma_unit(0) + 4096, tid);
    CPA_COMMIT();
    prefW(smB + MA_W0 + UNIT_BYTES,              ma_unit(1),        tid);
    prefW(smB + MA_W0 + UNIT_BYTES + WBUF_BYTES, ma_unit(1) + 4096, tid);
    CPA_COMMIT();

    #pragma unroll
    for (int l = 0; l < 4; l++) {
        int u = tid + l*256;
        int r = u >> 5, q = u & 31;
        *(float4*)&Hs[r*128 + q*4] =
            *(const float4*)&h[(size_t)(rowBase+r)*128 + q*4];
    }
    __syncthreads();
    {
        float4 gg = ((const float4*)ls_g)[lane];
        float4 bb = ((const float4*)ls_b)[lane];
        #pragma unroll
        for (int p = 0; p < 4; p++) {
            int r = wid + p*8;
            float4 v = *(float4*)&Hs[r*128 + lane*4];
            float s = v.x + v.y + v.z + v.w;
            #pragma unroll
            for (int o = 16; o; o >>= 1) s += __shfl_xor_sync(0xffffffffu, s, o);
            float mu = s * (1.0f/128.0f);
            float dx = v.x-mu, dy = v.y-mu, dz = v.z-mu, dw = v.w-mu;
            float q = dx*dx + dy*dy + dz*dz + dw*dw;
            #pragma unroll
            for (int o = 16; o; o >>= 1) q += __shfl_xor_sync(0xffffffffu, q, o);
            float rs = rsqrtf(q * (1.0f/128.0f) + EPSLN);
            XN[r*68 + lane*2]   = pk2(dx*rs*gg.x + bb.x, dy*rs*gg.y + bb.y);
            XN[r*68 + lane*2+1] = pk2(dz*rs*gg.z + bb.z, dw*rs*gg.w + bb.w);
            HB[r*68 + lane*2]   = pk2(v.x, v.y);
            HB[r*68 + lane*2+1] = pk2(v.z, v.w);
        }
    }

    #pragma unroll 1
    for (int u = 0; u < 10; u++) {
        int ubuf = MA_W0 + (u & 1)*UNIT_BYTES;
        int aOff = (u == 0) ? MA_XN : (u == 1) ? MA_T1 : MA_HB;
        float c[4][4] = {};
        CPA_WAIT1(); __syncthreads();
        cmpW(c, smB, ubuf,              aOff, 68, 0,  tid);
        cmpW(c, smB, ubuf + WBUF_BYTES, aOff, 68, 32, tid);
        if (u == 0) {
            #pragma unroll
            for (int nt = 0; nt < 4; nt++) {
                int n0 = warp_n*32 + nt*8 + 2*q4;
                float2 bv = *(const float2*)&bs1[n0];
                T1[row0*68 + (n0>>1)] =
                    pk2(fmaxf(c[nt][0]+bv.x,0.f), fmaxf(c[nt][1]+bv.y,0.f));
                T1[row1*68 + (n0>>1)] =
                    pk2(fmaxf(c[nt][2]+bv.x,0.f), fmaxf(c[nt][3]+bv.y,0.f));
            }
        } else if (u == 1) {
            #pragma unroll
            for (int nt = 0; nt < 4; nt++) {
                int n0 = warp_n*32 + nt*8 + 2*q4;
                float2 bv = *(const float2*)&bs2[n0];
                float2 h0 = *(float2*)&Hs[row0*128 + n0];
                float2 h1 = *(float2*)&Hs[row1*128 + n0];
                *(float2*)&HDS[(size_t)(rowBase+row0)*128 + n0] =
                    make_float2(c[nt][0]+bv.x+h0.x, c[nt][1]+bv.y+h0.y);
                *(float2*)&HDS[(size_t)(rowBase+row1)*128 + n0] =
                    make_float2(c[nt][2]+bv.x+h1.x, c[nt][3]+bv.y+h1.y);
            }
        } else {
            int w1u = u - 2;
            int tau = w1u >> 1, half = w1u & 1;
            uint32_t* ob = (uint32_t*)((half ? Bb : Ab) +
                            ((size_t)tau*ROWS + rowBase)*128);
            #pragma unroll
            for (int nt = 0; nt < 4; nt++) {
                int n0 = warp_n*32 + nt*8 + 2*q4;
                float2 bv = half ? make_float2(0.f,0.f)
                                 : *(const float2*)&bi1[tau*128 + n0];
                ob[row0*64 + (n0>>1)] = pk2(c[nt][0]+bv.x, c[nt][1]+bv.y);
                ob[row1*64 + (n0>>1)] = pk2(c[nt][2]+bv.x, c[nt][3]+bv.y);
            }
        }
        __syncthreads();
        if (u + 2 < 10) {
            prefW(smB + ubuf,              ma_unit(u+2),        tid);
            prefW(smB + ubuf + WBUF_BYTES, ma_unit(u+2) + 4096, tid);
        }
        CPA_COMMIT();
    }
}

// ---------------- HMMA fused inter kernel (dual-buffer epilogue) ------------
#define WSTR 68
#define SM_AS   0
#define SM_BS   17408
#define SM_W2   34816
#define SM_WM   69632
#define SM_BI2  86016
#define SM_TOT  86528

__global__ void __launch_bounds__(256, 1) inter_hmma_kernel(
    const __nv_bfloat16* __restrict__ gAb, const __nv_bfloat16* __restrict__ gBb,
    const float* __restrict__ bi2,
    __nv_bfloat16* __restrict__ gSb, float* __restrict__ gW)
{
    extern __shared__ char sm[];
    uint32_t* Asm  = (uint32_t*)(sm + SM_AS);
    uint32_t* Bsm  = (uint32_t*)(sm + SM_BS);
    uint32_t* W2s  = (uint32_t*)(sm + SM_W2);
    float* Wmat = (float*)(sm + SM_WM);
    float* bi2s = (float*)(sm + SM_BI2);

    int tid = threadIdx.x, lane = tid & 31, wid = tid >> 5;
    int b = blockIdx.x, tau = blockIdx.y;
    int g = lane >> 2, q4 = lane & 3;
    int warp_p  = wid >> 2;
    int warp_j  = (wid >> 1) & 1;
    int warp_nh = wid & 1;
    int lA_row = lane & 15, lA_kw = (lane >> 4) << 2;
    int lB_row = (lane & 7) + ((lane >> 4) << 3);
    int lB_kw  = ((lane >> 3) & 1) << 2;
    uint32_t BsB = s2u(sm) + SM_BS, W2B = s2u(sm) + SM_W2;

    const uint4* Ag = (const uint4*)(gAb + ((size_t)tau*ROWS + b*64)*128);
    const uint4* Bg = (const uint4*)(gBb + ((size_t)tau*ROWS + b*64)*128);
    #pragma unroll
    for (int l = 0; l < 4; l++) {
        int v = tid + l*256;
        int row = v >> 4, wq = v & 15;
        *(uint4*)&Asm[row*WSTR + wq*4] = Ag[row*16 + wq];
        *(uint4*)&Bsm[row*WSTR + wq*4] = Bg[row*16 + wq];
    }
    {
        const uint4* src = (const uint4*)(g_Wp + W_WI2F + tau*8192);
        #pragma unroll
        for (int l = 0; l < 8; l++) {
            int u = tid + l*256;
            int n = u >> 4, q = u & 15;
            *(uint4*)&W2s[n*WSTR + q*4] = src[u];
        }
    }
    {
        const float4* Wg4 = (const float4*)(g_Wm + (((size_t)tau*64 + b) << 12));
        #pragma unroll
        for (int l = 0; l < 4; l++)
            ((float4*)Wmat)[tid + l*256] = Wg4[tid + l*256];
    }
    if (tid < 128) bi2s[tid] = bi2[tau*128 + tid];
    __syncthreads();

    if (tid < 64) {
        float s = 0.f;
        #pragma unroll 8
        for (int i = 0; i < 64; i++) s += Wmat[i*64 + tid];
        gW[(size_t)(b*64 + tid)*4 + tau] = s;
    }

    float bi2v[8][2];
    #pragma unroll
    for (int nn = 0; nn < 8; nn++) {
        int n0 = warp_nh*64 + nn*8 + 2*q4;
        bi2v[nn][0] = bi2s[n0];
        bi2v[nn][1] = bi2s[n0 + 1];
    }

    float S[2][8][4] = {};

    for (int it = 0; it < 32; it++) {
        int i = 2*it + warp_p;
        float c[2][8][4] = {};
        #pragma unroll
        for (int kk = 0; kk < 8; kk++) {
            uint32_t aw0 = Asm[i*WSTR + kk*8 + q4];
            uint32_t aw1 = Asm[i*WSTR + kk*8 + 4 + q4];
            uint32_t wf[4][4];
            #pragma unroll
            for (int nf = 0; nf < 4; nf++)
                ldmx4(wf[nf], W2B + ((warp_nh*64 + nf*16 + lB_row)*WSTR
                                     + kk*8 + lB_kw)*4);
            #pragma unroll
            for (int mt = 0; mt < 2; mt++) {
                uint32_t xb[4], x[4];
                ldmx4(xb, BsB + ((warp_j*32 + mt*16 + lA_row)*WSTR
                                 + kk*8 + lA_kw)*4);
                x[0] = addrelu2(xb[0], aw0);
                x[1] = addrelu2(xb[1], aw0);
                x[2] = addrelu2(xb[2], aw1);
                x[3] = addrelu2(xb[3], aw1);
                #pragma unroll
                for (int nf = 0; nf < 4; nf++) {
                    mma16816(c[mt][2*nf],   x, wf[nf][0], wf[nf][1]);
                    mma16816(c[mt][2*nf+1], x, wf[nf][2], wf[nf][3]);
                }
            }
        }
        #pragma unroll
        for (int mt = 0; mt < 2; mt++) {
            int jr = warp_j*32 + mt*16 + g;
            float w0 = Wmat[i*64 + jr];
            float w1 = Wmat[i*64 + jr + 8];
            #pragma unroll
            for (int nn = 0; nn < 8; nn++) {
                S[mt][nn][0] += w0*fmaxf(c[mt][nn][0] + bi2v[nn][0], 0.f);
                S[mt][nn][1] += w0*fmaxf(c[mt][nn][1] + bi2v[nn][1], 0.f);
                S[mt][nn][2] += w1*fmaxf(c[mt][nn][2] + bi2v[nn][0], 0.f);
                S[mt][nn][3] += w1*fmaxf(c[mt][nn][3] + bi2v[nn][1], 0.f);
            }
        }
    }

    // dual-buffer parity combine: warp_p=0 -> S0 (W2 area), warp_p=1 -> S1
    // (Asm/Bsm area, 34816 B contiguous from 0). One barrier, no RMW.
    float* S0 = (float*)(sm + SM_W2);
    float* S1 = (float*)(sm + SM_AS);
    __syncthreads();
    {
        float* Sd = warp_p ? S1 : S0;
        #pragma unroll
        for (int mt = 0; mt < 2; mt++) {
            int j = warp_j*32 + mt*16 + g;
            #pragma unroll
            for (int nn = 0; nn < 8; nn++) {
                int n = warp_nh*64 + nn*8 + 2*q4;
                *(float2*)&Sd[j*132 + n] =
                    make_float2(S[mt][nn][0], S[mt][nn][1]);
                *(float2*)&Sd[(j+8)*132 + n] =
                    make_float2(S[mt][nn][2], S[mt][nn][3]);
            }
        }
    }
    __syncthreads();
    for (int q = tid; q < 2048; q += 256) {
        int j = q >> 5, w = q & 31;
        float4 v0 = *(float4*)&S0[j*132 + w*4];
        float4 v1 = *(float4*)&S1[j*132 + w*4];
        uint2 u = make_uint2(pk2(v0.x + v1.x, v0.y + v1.y),
                             pk2(v0.z + v1.z, v0.w + v1.w));
        *(uint2*)&gSb[(size_t)(b*64 + j)*512 + tau*128 + w*4] = u;
    }
}

// ---------------- megaB: wi3 + LN256 + update MLP (unit-batched, depth-2) ---
#define MB_AS0  0
#define MB_DI   18432
#define MB_CN   35328
#define MB_T1   52224
#define MB_W0   60928
#define MB_TOT  134656

__device__ __forceinline__ const uint32_t* mb_unit(int u){
    if (u < 4)  return g_Wp + W_WI3 + u*8192;
    if (u < 6)  return g_Wp + W_WU1 + (u-4)*8192;
    return g_Wp + W_WU2;
}

__global__ void __launch_bounds__(256) megaB_kernel(
    const __nv_bfloat16* __restrict__ Sb, const float* __restrict__ Wq,
    const float* __restrict__ bi3, const float* __restrict__ HDS,
    const float* __restrict__ lu_g, const float* __restrict__ lu_b,
    const float* __restrict__ bu1, const float* __restrict__ bu2,
    const float* __restrict__ hResid, float* __restrict__ hOut)
{
    extern __shared__ char sm[];
    float*    DIs = (float*)(sm + MB_DI);
    uint32_t* CN = (uint32_t*)(sm + MB_CN);
    uint32_t* T1 = (uint32_t*)(sm + MB_T1);
    uint32_t smB = s2u(sm);
    int tid = threadIdx.x, lane = tid & 31, wid = tid >> 5;
    int rowBase = blockIdx.x * 32;
    int g = lane >> 2, q4 = lane & 3;
    int warp_m = wid >> 2, warp_n = wid & 3;
    int row0 = warp_m*16 + g, row1 = row0 + 8;

    prefW(smB + MB_W0,              mb_unit(0),        tid);
    prefW(smB + MB_W0 + WBUF_BYTES, mb_unit(0) + 4096, tid);
    prefS(smB + MB_AS0,        Sb, rowBase, 0, tid);
    prefS(smB + MB_AS0 + 4608, Sb, rowBase, 1, tid);
    CPA_COMMIT();
    prefW(smB + MB_W0 + UNIT_BYTES,              mb_unit(1),        tid);
    prefW(smB + MB_W0 + UNIT_BYTES + WBUF_BYTES, mb_unit(1) + 4096, tid);
    prefS(smB + MB_AS0 + 9216,  Sb, rowBase, 2, tid);
    prefS(smB + MB_AS0 + 13824, Sb, rowBase, 3, tid);
    CPA_COMMIT();

    float c[4][4] = {};
    #pragma unroll 1
    for (int u = 0; u < 7; u++) {
        int ubuf = MB_W0 + (u & 1)*UNIT_BYTES;
        CPA_WAIT1(); __syncthreads();
        if (u < 4) {
            int asb = MB_AS0 + (u & 1)*9216;
            cmpW(c, smB, ubuf,              asb,        36, 0, tid);
            cmpW(c, smB, ubuf + WBUF_BYTES, asb + 4608, 36, 0, tid);
        } else if (u < 6) {
            int aCh = (u - 4)*64;
            cmpW(c, smB, ubuf,              MB_CN, 132, aCh,      tid);
            cmpW(c, smB, ubuf + WBUF_BYTES, MB_CN, 132, aCh + 32, tid);
        } else {
            cmpW(c, smB, ubuf,              MB_T1, 68, 0,  tid);
            cmpW(c, smB, ubuf + WBUF_BYTES, MB_T1, 68, 32, tid);
        }

        if (u == 3) {
            float4 wa = *(const float4*)&Wq[(size_t)(rowBase+row0)*4];
            float4 wb = *(const float4*)&Wq[(size_t)(rowBase+row1)*4];
            #pragma unroll
            for (int nt = 0; nt < 4; nt++) {
                int n0 = warp_n*32 + nt*8 + 2*q4;
                float2 v0 = make_float2(c[nt][0], c[nt][1]);
                float2 v1 = make_float2(c[nt][2], c[nt][3]);
                #pragma unroll
                for (int t = 0; t < 4; t++) {
                    float wta = (t==0)?wa.x:(t==1)?wa.y:(t==2)?wa.z:wa.w;
                    float wtb = (t==0)?wb.x:(t==1)?wb.y:(t==2)?wb.z:wb.w;
                    float2 rb = *(const float2*)&bi3[t*128 + n0];
                    v0.x += wta*rb.x; v0.y += wta*rb.y;
                    v1.x += wtb*rb.x; v1.y += wtb*rb.y;
                }
                *(float2*)&DIs[row0*132 + n0] = v0;
                *(float2*)&DIs[row1*132 + n0] = v1;
            }
            #pragma unroll
            for (int a = 0; a < 4; a++)
                #pragma unroll
                for (int d = 0; d < 4; d++) c[a][d] = 0.f;
            __syncthreads();
            float4 g0 = ((const float4*)lu_g)[lane];
            float4 g1 = ((const float4*)lu_g)[32 + lane];
            float4 c0 = ((const float4*)lu_b)[lane];
            float4 c1 = ((const float4*)lu_b)[32 + lane];
            #pragma unroll
            for (int p = 0; p < 4; p++) {
                int r = wid + p*8;
                float4 v0 = *(const float4*)&HDS[(size_t)(rowBase+r)*128 + lane*4];
                float4 v1 = *(float4*)&DIs[r*132 + lane*4];
                float s = v0.x+v0.y+v0.z+v0.w + v1.x+v1.y+v1.z+v1.w;
                #pragma unroll
                for (int o = 16; o; o >>= 1) s += __shfl_xor_sync(0xffffffffu, s, o);
                float mu = s * (1.0f/256.0f);
                float a0=v0.x-mu, a1=v0.y-mu, a2=v0.z-mu, a3=v0.w-mu;
                float b0=v1.x-mu, b1=v1.y-mu, b2=v1.z-mu, b3=v1.w-mu;
                float q = a0*a0+a1*a1+a2*a2+a3*a3 + b0*b0+b1*b1+b2*b2+b3*b3;
                #pragma unroll
                for (int o = 16; o; o >>= 1) q += __shfl_xor_sync(0xffffffffu, q, o);
                float rs = rsqrtf(q * (1.0f/256.0f) + EPSLN);
                CN[r*132 + lane*2]        = pk2(a0*rs*g0.x + c0.x, a1*rs*g0.y + c0.y);
                CN[r*132 + lane*2 + 1]    = pk2(a2*rs*g0.z + c0.z, a3*rs*g0.w + c0.w);
                CN[r*132 + 64 + lane*2]   = pk2(b0*rs*g1.x + c1.x, b1*rs*g1.y + c1.y);
                CN[r*132 + 64 + lane*2+1] = pk2(b2*rs*g1.z + c1.z, b3*rs*g1.w + c1.w);
            }
        } else if (u == 5) {
            #pragma unroll
            for (int nt = 0; nt < 4; nt++) {
                int n0 = warp_n*32 + nt*8 + 2*q4;
                float2 bv = *(const float2*)&bu1[n0];
                T1[row0*68 + (n0>>1)] =
                    pk2(fmaxf(c[nt][0]+bv.x,0.f), fmaxf(c[nt][1]+bv.y,0.f));
                T1[row1*68 + (n0>>1)] =
                    pk2(fmaxf(c[nt][2]+bv.x,0.f), fmaxf(c[nt][3]+bv.y,0.f));
            }
            #pragma unroll
            for (int a = 0; a < 4; a++)
                #pragma unroll
                for (int d = 0; d < 4; d++) c[a][d] = 0.f;
        } else if (u == 6) {
            #pragma unroll
            for (int nt = 0; nt < 4; nt++) {
                int n0 = warp_n*32 + nt*8 + 2*q4;
                float2 bv = *(const float2*)&bu2[n0];
                float2 h0 = *(const float2*)&hResid[(size_t)(rowBase+row0)*128 + n0];
                float2 h1 = *(const float2*)&hResid[(size_t)(rowBase+row1)*128 + n0];
                *(float2*)&hOut[(size_t)(rowBase+row0)*128 + n0] =
                    make_float2(c[nt][0]+bv.x+h0.x, c[nt][1]+bv.y+h0.y);
                *(float2*)&hOut[(size_t)(rowBase+row1)*128 + n0] =
                    make_float2(c[nt][2]+bv.x+h1.x, c[nt][3]+bv.y+h1.y);
            }
        }
        __syncthreads();
        if (u + 2 < 7) {
            int nu = u + 2;
            prefW(smB + ubuf,              mb_unit(nu),        tid);
            prefW(smB + ubuf + WBUF_BYTES, mb_unit(nu) + 4096, tid);
            if (nu < 4) {
                prefS(smB + MB_AS0 + (u & 1)*9216,        Sb, rowBase, nu*2,   tid);
                prefS(smB + MB_AS0 + (u & 1)*9216 + 4608, Sb, rowBase, nu*2+1, tid);
            }
        }
        CPA_COMMIT();
    }
}

// ---------------- megaBA: fused megaB(it0) + megaA(it1) ---------------------
#define BA_W0   0
#define BA_AS   73728
#define BA_DI   92160
#define BA_CN   109056
#define BA_T1B  125952
#define BA_HS   134656
#define BA_XN   151040
#define BA_HB   159744
#define BA_T1A  168448
#define BA_TOT  177152

__device__ __forceinline__ const uint32_t* ba_unit(int g){
    if (g < 4)  return g_Wp + W_WI3 + g*8192;
    if (g < 6)  return g_Wp + W_WU1 + (g-4)*8192;
    if (g == 6) return g_Wp + W_WU2;
    if (g == 7) return g_Wp + W_WS1;
    if (g == 8) return g_Wp + W_WS2;
    return g_Wp + W_WI1 + (g-9)*8192;
}

__global__ void __launch_bounds__(256) megaBA_kernel(
    const __nv_bfloat16* __restrict__ Sb, const float* __restrict__ Wq,
    const float* __restrict__ bi3, const float* __restrict__ HDS,
    const float* __restrict__ lu_g, const float* __restrict__ lu_b,
    const float* __restrict__ bu1, const float* __restrict__ bu2,
    const float* __restrict__ hResid, float* __restrict__ hOut,
    const float* __restrict__ ls_g, const float* __restrict__ ls_b,
    const float* __restrict__ bs1, const float* __restrict__ bs2,
    const float* __restrict__ bi1, float* __restrict__ HDSo,
    __nv_bfloat16* __restrict__ Ab, __nv_bfloat16* __restrict__ Bb)
{
    extern __shared__ char sm[];
    float*    DIs = (float*)(sm + BA_DI);
    uint32_t* CN  = (uint32_t*)(sm + BA_CN);
    uint32_t* T1B = (uint32_t*)(sm + BA_T1B);
    float*    Hs  = (float*)(sm + BA_HS);
    uint32_t* XN  = (uint32_t*)(sm + BA_XN);
    uint32_t* HB  = (uint32_t*)(sm + BA_HB);
    uint32_t* T1A = (uint32_t*)(sm + BA_T1A);
    uint32_t smB = s2u(sm);
    int tid = threadIdx.x, lane = tid & 31, wid = tid >> 5;
    int rowBase = blockIdx.x * 32;
    int g = lane >> 2, q4 = lane & 3;
    int warp_m = wid >> 2, warp_n = wid & 3;
    int row0 = warp_m*16 + g, row1 = row0 + 8;

    prefW(smB + BA_W0,              ba_unit(0),        tid);
    prefW(smB + BA_W0 + WBUF_BYTES, ba_unit(0) + 4096, tid);
    prefS(smB + BA_AS,        Sb, rowBase, 0, tid);
    prefS(smB + BA_AS + 4608, Sb, rowBase, 1, tid);
    CPA_COMMIT();
    prefW(smB + BA_W0 + UNIT_BYTES,              ba_unit(1),        tid);
    prefW(smB + BA_W0 + UNIT_BYTES + WBUF_BYTES, ba_unit(1) + 4096, tid);
    prefS(smB + BA_AS + 9216,  Sb, rowBase, 2, tid);
    prefS(smB + BA_AS + 13824, Sb, rowBase, 3, tid);
    CPA_COMMIT();

    float c[4][4] = {};
    #pragma unroll 1
    for (int u = 0; u < 17; u++) {
        int ubuf = BA_W0 + (u & 1)*UNIT_BYTES;
        CPA_WAIT1(); __syncthreads();
        if (u < 4) {
            int asb = BA_AS + (u & 1)*9216;
            cmpW(c, smB, ubuf,              asb,        36, 0, tid);
            cmpW(c, smB, ubuf + WBUF_BYTES, asb + 4608, 36, 0, tid);
        } else if (u < 6) {
            int aCh = (u - 4)*64;
            cmpW(c, smB, ubuf,              BA_CN, 132, aCh,      tid);
            cmpW(c, smB, ubuf + WBUF_BYTES, BA_CN, 132, aCh + 32, tid);
        } else if (u == 6) {
            cmpW(c, smB, ubuf,              BA_T1B, 68, 0,  tid);
            cmpW(c, smB, ubuf + WBUF_BYTES, BA_T1B, 68, 32, tid);
        } else if (u == 7) {
            cmpW(c, smB, ubuf,              BA_XN, 68, 0,  tid);
            cmpW(c, smB, ubuf + WBUF_BYTES, BA_XN, 68, 32, tid);
        } else if (u == 8) {
            cmpW(c, smB, ubuf,              BA_T1A, 68, 0,  tid);
            cmpW(c, smB, ubuf + WBUF_BYTES, BA_T1A, 68, 32, tid);
        } else {
            cmpW(c, smB, ubuf,              BA_HB, 68, 0,  tid);
            cmpW(c, smB, ubuf + WBUF_BYTES, BA_HB, 68, 32, tid);
        }

        if (u == 3) {
            float4 wa = *(const float4*)&Wq[(size_t)(rowBase+row0)*4];
            float4 wb = *(const float4*)&Wq[(size_t)(rowBase+row1)*4];
            #pragma unroll
            for (int nt = 0; nt < 4; nt++) {
                int n0 = warp_n*32 + nt*8 + 2*q4;
                float2 v0 = make_float2(c[nt][0], c[nt][1]);
                float2 v1 = make_float2(c[nt][2], c[nt][3]);
                #pragma unroll
                for (int t = 0; t < 4; t++) {
                    float wta = (t==0)?wa.x:(t==1)?wa.y:(t==2)?wa.z:wa.w;
                    float wtb = (t==0)?wb.x:(t==1)?wb.y:(t==2)?wb.z:wb.w;
                    float2 rb = *(const float2*)&bi3[t*128 + n0];
                    v0.x += wta*rb.x; v0.y += wta*rb.y;
                    v1.x += wtb*rb.x; v1.y += wtb*rb.y;
                }
                *(float2*)&DIs[row0*132 + n0] = v0;
                *(float2*)&DIs[row1*132 + n0] = v1;
            }
            #pragma unroll
            for (int a = 0; a < 4; a++)
                #pragma unroll
                for (int d = 0; d < 4; d++) c[a][d] = 0.f;
            __syncthreads();
            float4 g0 = ((const float4*)lu_g)[lane];
            float4 g1 = ((const float4*)lu_g)[32 + lane];
            float4 c0 = ((const float4*)lu_b)[lane];
            float4 c1 = ((const float4*)lu_b)[32 + lane];
            #pragma unroll
            for (int p = 0; p < 4; p++) {
                int r = wid + p*8;
                float4 v0 = *(const float4*)&HDS[(size_t)(rowBase+r)*128 + lane*4];
                float4 v1 = *(float4*)&DIs[r*132 + lane*4];
                float s = v0.x+v0.y+v0.z+v0.w + v1.x+v1.y+v1.z+v1.w;
                #pragma unroll
                for (int o = 16; o; o >>= 1) s += __shfl_xor_sync(0xffffffffu, s, o);
                float mu = s * (1.0f/256.0f);
                float a0=v0.x-mu, a1=v0.y-mu, a2=v0.z-mu, a3=v0.w-mu;
                float b0=v1.x-mu, b1=v1.y-mu, b2=v1.z-mu, b3=v1.w-mu;
                float q = a0*a0+a1*a1+a2*a2+a3*a3 + b0*b0+b1*b1+b2*b2+b3*b3;
                #pragma unroll
                for (int o = 16; o; o >>= 1) q += __shfl_xor_sync(0xffffffffu, q, o);
                float rs = rsqrtf(q * (1.0f/256.0f) + EPSLN);
                CN[r*132 + lane*2]        = pk2(a0*rs*g0.x + c0.x, a1*rs*g0.y + c0.y);
                CN[r*132 + lane*2 + 1]    = pk2(a2*rs*g0.z + c0.z, a3*rs*g0.w + c0.w);
                CN[r*132 + 64 + lane*2]   = pk2(b0*rs*g1.x + c1.x, b1*rs*g1.y + c1.y);
                CN[r*132 + 64 + lane*2+1] = pk2(b2*rs*g1.z + c1.z, b3*rs*g1.w + c1.w);
            }
        } else if (u == 5) {
            #pragma unroll
            for (int nt = 0; nt < 4; nt++) {
                int n0 = warp_n*32 + nt*8 + 2*q4;
                float2 bv = *(const float2*)&bu1[n0];
                T1B[row0*68 + (n0>>1)] =
                    pk2(fmaxf(c[nt][0]+bv.x,0.f), fmaxf(c[nt][1]+bv.y,0.f));
                T1B[row1*68 + (n0>>1)] =
                    pk2(fmaxf(c[nt][2]+bv.x,0.f), fmaxf(c[nt][3]+bv.y,0.f));
            }
            #pragma unroll
            for (int a = 0; a < 4; a++)
                #pragma unroll
                for (int d = 0; d < 4; d++) c[a][d] = 0.f;
        } else if (u == 6) {
            #pragma unroll
            for (int nt = 0; nt < 4; nt++) {
                int n0 = warp_n*32 + nt*8 + 2*q4;
                float2 bv = *(const float2*)&bu2[n0];
                float2 h0 = *(const float2*)&hResid[(size_t)(rowBase+row0)*128 + n0];
                float2 h1 = *(const float2*)&hResid[(size_t)(rowBase+row1)*128 + n0];
                float2 o0 = make_float2(c[nt][0]+bv.x+h0.x, c[nt][1]+bv.y+h0.y);
                float2 o1 = make_float2(c[nt][2]+bv.x+h1.x, c[nt][3]+bv.y+h1.y);
                *(float2*)&hOut[(size_t)(rowBase+row0)*128 + n0] = o0;
                *(float2*)&hOut[(size_t)(rowBase+row1)*128 + n0] = o1;
                *(float2*)&Hs[row0*128 + n0] = o0;
                *(float2*)&Hs[row1*128 + n0] = o1;
            }
            #pragma unroll
            for (int a = 0; a < 4; a++)
                #pragma unroll
                for (int d = 0; d < 4; d++) c[a][d] = 0.f;
            __syncthreads();
            float4 gg = ((const float4*)ls_g)[lane];
            float4 bb = ((const float4*)ls_b)[lane];
            #pragma unroll
            for (int p = 0; p < 4; p++) {
                int r = wid + p*8;
                float4 v = *(float4*)&Hs[r*128 + lane*4];
                float s = v.x + v.y + v.z + v.w;
                #pragma unroll
                for (int o = 16; o; o >>= 1) s += __shfl_xor_sync(0xffffffffu, s, o);
                float mu = s * (1.0f/128.0f);
                float dx = v.x-mu, dy = v.y-mu, dz = v.z-mu, dw = v.w-mu;
                float q = dx*dx + dy*dy + dz*dz + dw*dw;
                #pragma unroll
                for (int o = 16; o; o >>= 1) q += __shfl_xor_sync(0xffffffffu, q, o);
                float rs = rsqrtf(q * (1.0f/128.0f) + EPSLN);
                XN[r*68 + lane*2]   = pk2(dx*rs*gg.x + bb.x, dy*rs*gg.y + bb.y);
                XN[r*68 + lane*2+1] = pk2(dz*rs*gg.z + bb.z, dw*rs*gg.w + bb.w);
                HB[r*68 + lane*2]   = pk2(v.x, v.y);
                HB[r*68 + lane*2+1] = pk2(v.z, v.w);
            }
        } else if (u == 7) {
            #pragma unroll
            for (int nt = 0; nt < 4; nt++) {
                int n0 = warp_n*32 + nt*8 + 2*q4;
                float2 bv = *(const float2*)&bs1[n0];
                T1A[row0*68 + (n0>>1)] =
                    pk2(fmaxf(c[nt][0]+bv.x,0.f), fmaxf(c[nt][1]+bv.y,0.f));
                T1A[row1*68 + (n0>>1)] =
                    pk2(fmaxf(c[nt][2]+bv.x,0.f), fmaxf(c[nt][3]+bv.y,0.f));
            }
            #pragma unroll
            for (int a = 0; a < 4; a++)
                #pragma unroll
                for (int d = 0; d < 4; d++) c[a][d] = 0.f;
        } else if (u == 8) {
            #pragma unroll
            for (int nt = 0; nt < 4; nt++) {
                int n0 = warp_n*32 + nt*8 + 2*q4;
                float2 bv = *(const float2*)&bs2[n0];
                float2 h0 = *(float2*)&Hs[row0*128 + n0];
                float2 h1 = *(float2*)&Hs[row1*128 + n0];
                *(float2*)&HDSo[(size_t)(rowBase+row0)*128 + n0] =
                    make_float2(c[nt][0]+bv.x+h0.x, c[nt][1]+bv.y+h0.y);
                *(float2*)&HDSo[(size_t)(rowBase+row1)*128 + n0] =
                    make_float2(c[nt][2]+bv.x+h1.x, c[nt][3]+bv.y+h1.y);
            }
            #pragma unroll
            for (int a = 0; a < 4; a++)
                #pragma unroll
                for (int d = 0; d < 4; d++) c[a][d] = 0.f;
        } else if (u >= 9) {
            int w1u = u - 9;
            int tau = w1u >> 1, half = w1u & 1;
            uint32_t* ob = (uint32_t*)((half ? Bb : Ab) +
                            ((size_t)tau*ROWS + rowBase)*128);
            #pragma unroll
            for (int nt = 0; nt < 4; nt++) {
                int n0 = warp_n*32 + nt*8 + 2*q4;
                float2 bv = half ? make_float2(0.f,0.f)
                                 : *(const float2*)&bi1[tau*128 + n0];
                ob[row0*64 + (n0>>1)] = pk2(c[nt][0]+bv.x, c[nt][1]+bv.y);
                ob[row1*64 + (n0>>1)] = pk2(c[nt][2]+bv.x, c[nt][3]+bv.y);
            }
            #pragma unroll
            for (int a = 0; a < 4; a++)
                #pragma unroll
                for (int d = 0; d < 4; d++) c[a][d] = 0.f;
        }
        __syncthreads();
        int t = u + 2;
        if (t < 17) {
            prefW(smB + ubuf,              ba_unit(t),        tid);
            prefW(smB + ubuf + WBUF_BYTES, ba_unit(t) + 4096, tid);
            if (t < 4) {
                prefS(smB + BA_AS + (u & 1)*9216,        Sb, rowBase, t*2,   tid);
                prefS(smB + BA_AS + (u & 1)*9216 + 4608, Sb, rowBase, t*2+1, tid);
            }
        }
        CPA_COMMIT();
    }
}

// ---------------- host orchestration ----------------
extern "C" void kernel_launch(void* const* d_in, const int* in_sizes, int n_in,
                              void* d_out, int out_size)
{
    const float* slots = (const float*)d_in[0];
    const float* ep    = (const float*)d_in[1];
    const float* et    = (const float*)d_in[2];
    const float* ls_g  = (const float*)d_in[3];
    const float* ls_b  = (const float*)d_in[4];
    const float* ws1   = (const float*)d_in[5];
    const float* bs1   = (const float*)d_in[6];
    const float* ws2   = (const float*)d_in[7];
    const float* bs2   = (const float*)d_in[8];
    const float* wi1   = (const float*)d_in[9];
    const float* bi1   = (const float*)d_in[10];
    const float* wi2   = (const float*)d_in[11];
    const float* bi2   = (const float*)d_in[12];
    const float* wi3   = (const float*)d_in[13];
    const float* bi3   = (const float*)d_in[14];
    const float* lu_g  = (const float*)d_in[15];
    const float* lu_b  = (const float*)d_in[16];
    const float* wu1   = (const float*)d_in[17];
    const float* bu1   = (const float*)d_in[18];
    const float* wu2   = (const float*)d_in[19];
    const float* bu2   = (const float*)d_in[20];
    float* out = (float*)d_out;

    float *HDS, *H, *W;
    __nv_bfloat16 *Ab, *Bb, *Sb;
    cudaGetSymbolAddress((void**)&HDS, g_HDS);
    cudaGetSymbolAddress((void**)&H,   g_H);
    cudaGetSymbolAddress((void**)&W,   g_W);
    cudaGetSymbolAddress((void**)&Ab,  g_Ab);
    cudaGetSymbolAddress((void**)&Bb,  g_Bb);
    cudaGetSymbolAddress((void**)&Sb,  g_Sb);

    cudaFuncSetAttribute(megaA_kernel,
        cudaFuncAttributeMaxDynamicSharedMemorySize, MA_TOT);
    cudaFuncSetAttribute(megaB_kernel,
        cudaFuncAttributeMaxDynamicSharedMemorySize, MB_TOT);
    cudaFuncSetAttribute(megaBA_kernel,
        cudaFuncAttributeMaxDynamicSharedMemorySize, BA_TOT);
    cudaFuncSetAttribute(inter_hmma_kernel,
        cudaFuncAttributeMaxDynamicSharedMemorySize, SM_TOT);

    prep_weights<<<(PREP_TOTAL+255)/256, 256>>>(ws1, ws2, wu2, wi3, wu1,
                                                wi1, wi2, ep, et);

    // iteration 0
    megaA_kernel<<<128, 256, MA_TOT>>>(slots, ls_g, ls_b, bs1, bs2, bi1,
                                       HDS, Ab, Bb);
    inter_hmma_kernel<<<dim3(BB, TT), 256, SM_TOT>>>(Ab, Bb, bi2, Sb, W);
    // fused: megaB(it0) -> H ; megaA(it1) -> HDS, Ab, Bb
    megaBA_kernel<<<128, 256, BA_TOT>>>(Sb, W, bi3, HDS, lu_g, lu_b,
                                        bu1, bu2, slots, H,
                                        ls_g, ls_b, bs1, bs2, bi1,
                                        HDS, Ab, Bb);
    // iteration 1
    inter_hmma_kernel<<<dim3(BB, TT), 256, SM_TOT>>>(Ab, Bb, bi2, Sb, W);
    megaB_kernel<<<128, 256, MB_TOT>>>(Sb, W, bi3, HDS, lu_g, lu_b,
                                       bu1, bu2, H, out);
}